// round 12
// baseline (speedup 1.0000x reference)
#include <cuda_runtime.h>
#include <cuda_bf16.h>
#include <math.h>
#include <cstdint>

// Problem constants
#define BSZ   4096        // B*S tokens
#define HD    1024        // hidden
#define NE    16          // experts
#define CAPM  768         // CAP_MAX
#define HI2   512         // H/2
#define NT    1536        // combined N (W1 | Wi1)

static const long long D_SZ    = (long long)BSZ * NE * CAPM;       // 50331648
static const long long COMB_OFF= D_SZ;
static const long long RP_OFF  = 2 * D_SZ;                         // 100663296
static const long long AUX_OFF = RP_OFF + (long long)BSZ * NE;     // 100728832
static const long long IMP_OFF = AUX_OFF + 1;                      // 100728833

// Scratch (device globals; no cudaMalloc allowed)
__device__ __nv_bfloat16 g_A0[(size_t)BSZ * HD];   // bf16 hi split of X
__device__ __nv_bfloat16 g_A1[(size_t)BSZ * HD];   // bf16 lo split of X
__device__ __nv_bfloat16 g_B0[(size_t)HD * NT];    // bf16 hi split of [W1|Wi1]
__device__ __nv_bfloat16 g_B1[(size_t)HD * NT];    // bf16 lo split
__device__ float g_logits[(size_t)BSZ * NE];       // router logits accumulator
__device__ float g_impacc[BSZ];                    // importance pre-sigmoid accumulator
__device__ float g_avg[HD];                  // column sums of X
__device__ float g_impsum;                   // sum of importance
__device__ float g_probsum[NE];              // sum of router probs per expert
__device__ float g_tkl[2];                   // top-k predictor logits
__device__ float g_aux;                      // aux loss accumulator
__device__ float g_tp[BSZ * 2];              // top-2 probs
__device__ int   g_te[BSZ * 2];              // top-2 expert ids
__device__ int   g_bar[4];                   // grid-barrier counters (zeroed per call)

// ===========================================================================
// PTX helpers (portable; nothing sm_103a-suffix-gated)
// ===========================================================================
__device__ __forceinline__ uint32_t smem_to_u32(const void* p) {
    uint32_t a;
    asm("{ .reg .u64 t; cvta.to.shared.u64 t, %1; cvt.u32.u64 %0, t; }" : "=r"(a) : "l"(p));
    return a;
}
#define LDSM4(d, a) \
    asm volatile("ldmatrix.sync.aligned.m8n8.x4.shared.b16 {%0,%1,%2,%3}, [%4];" \
        : "=r"((d)[0]), "=r"((d)[1]), "=r"((d)[2]), "=r"((d)[3]) : "r"(a))
#define LDSM4T(d, a) \
    asm volatile("ldmatrix.sync.aligned.m8n8.x4.trans.shared.b16 {%0,%1,%2,%3}, [%4];" \
        : "=r"((d)[0]), "=r"((d)[1]), "=r"((d)[2]), "=r"((d)[3]) : "r"(a))
#define MMA16816(c, a, b0, b1) \
    asm volatile("mma.sync.aligned.m16n8k16.row.col.f32.bf16.bf16.f32 " \
        "{%0,%1,%2,%3}, {%4,%5,%6,%7}, {%8,%9}, {%0,%1,%2,%3};" \
        : "+f"((c)[0]), "+f"((c)[1]), "+f"((c)[2]), "+f"((c)[3]) \
        : "r"((a)[0]), "r"((a)[1]), "r"((a)[2]), "r"((a)[3]), "r"(b0), "r"(b1))
#define CP16(s, g) \
    asm volatile("cp.async.cg.shared.global [%0], [%1], 16;" :: "r"(s), "l"(g))
#define CP_COMMIT() asm volatile("cp.async.commit_group;" ::: "memory")
#define CP_WAIT1()  asm volatile("cp.async.wait_group 1;" ::: "memory")
#define CP_WAIT0()  asm volatile("cp.async.wait_group 0;" ::: "memory")

// smem geometry (bytes): padded rows for conflict-free ldmatrix
#define AS_ROWB   80                     // 32 bf16 + pad -> 80B rows
#define BS_ROWB   272                    // 128 bf16 + pad -> 272B rows
#define A_SPLIT_B (64 * AS_ROWB)         // 5120
#define B_SPLIT_B (32 * BS_ROWB)         // 8704
#define B_OFF     (2 * A_SPLIT_B)        // 10240
#define BUF_B     (B_OFF + 2 * B_SPLIT_B)// 27648
#define STAGES    3
#define SMEMT     (STAGES * BUF_B)       // 82944

// ===========================================================================
// fused HMMA bf16-split GEMM with router/importance epilogue (unchanged R11)
// ===========================================================================
__global__ __launch_bounds__(256, 2)
void gemm_mma(const __nv_bfloat16* __restrict__ A0g, const __nv_bfloat16* __restrict__ A1g,
              const __nv_bfloat16* __restrict__ B0g, const __nv_bfloat16* __restrict__ B1g,
              const float* __restrict__ b1, const float* __restrict__ bi1,
              const float* __restrict__ W2, const float* __restrict__ Wi2) {
    extern __shared__ char smem[];
    const uint32_t sb = smem_to_u32(smem);
    const int tid = threadIdx.x, wid = tid >> 5, lane = tid & 31;
    const int m0 = blockIdx.y * 64;
    const int n0 = blockIdx.x * 128;

    const int ar = tid >> 2, acq = tid & 3;
    const int br = tid >> 3, bcq = tid & 7;
    const __nv_bfloat16* A0p = A0g + (size_t)(m0 + ar) * HD + acq * 8;
    const __nv_bfloat16* A1p = A1g + (size_t)(m0 + ar) * HD + acq * 8;
    const __nv_bfloat16* B0p = B0g + (size_t)br * NT + n0 + bcq * 16;
    const __nv_bfloat16* B1p = B1g + (size_t)br * NT + n0 + bcq * 16;
    const uint32_t asw = sb + (uint32_t)ar * AS_ROWB + acq * 16;
    const uint32_t bsw = sb + B_OFF + (uint32_t)br * BS_ROWB + bcq * 32;

    auto issue = [&](int it, int stg) {
        const uint32_t a = asw + stg * BUF_B;
        CP16(a,             A0p + it * 32);
        CP16(a + A_SPLIT_B, A1p + it * 32);
        const uint32_t b = bsw + stg * BUF_B;
        const __nv_bfloat16* pb0 = B0p + (size_t)it * 32 * NT;
        const __nv_bfloat16* pb1 = B1p + (size_t)it * 32 * NT;
        CP16(b,                  pb0);
        CP16(b + 16,             pb0 + 8);
        CP16(b + B_SPLIT_B,      pb1);
        CP16(b + B_SPLIT_B + 16, pb1 + 8);
        CP_COMMIT();
    };

    const int wm = wid >> 2, wn = wid & 3;
    const int mbase = wm * 32, nbase = wn * 32;
    const int l8 = lane & 7, lb8 = (lane >> 3) & 1, lhi = lane >> 4;
    const uint32_t aAddr = sb + (uint32_t)(mbase + l8 + 8 * lb8) * AS_ROWB + lhi * 16;
    const uint32_t bAddr = sb + B_OFF + (uint32_t)(l8 + 8 * lb8) * BS_ROWB
                         + (uint32_t)(nbase + lhi * 8) * 2;

    float acc[2][4][4];
#pragma unroll
    for (int i = 0; i < 2; i++)
#pragma unroll
        for (int j = 0; j < 4; j++)
#pragma unroll
            for (int c = 0; c < 4; c++) acc[i][j][c] = 0.f;

    issue(0, 0);
    issue(1, 1);

    int stg = 0;
    for (int it = 0; it < 32; it++) {
        if (it < 30) CP_WAIT1(); else CP_WAIT0();
        __syncthreads();
        if (it < 30) issue(it + 2, (it + 2) % STAGES);

        const uint32_t aB = aAddr + stg * BUF_B;
        const uint32_t bB = bAddr + stg * BUF_B;
#pragma unroll
        for (int ks = 0; ks < 2; ks++) {
            const uint32_t aK = aB + ks * 32;
            const uint32_t bK = bB + ks * 16 * BS_ROWB;
            uint32_t a0f[2][4], a1f[2][4], b0f[2][4], b1f[2][4];
#pragma unroll
            for (int nt = 0; nt < 2; nt++) LDSM4T(b0f[nt], bK + nt * 32);
#pragma unroll
            for (int ti = 0; ti < 2; ti++) LDSM4(a0f[ti], aK + ti * 16 * AS_ROWB);
#pragma unroll
            for (int ti = 0; ti < 2; ti++) LDSM4(a1f[ti], aK + A_SPLIT_B + ti * 16 * AS_ROWB);
#pragma unroll
            for (int nt = 0; nt < 2; nt++) LDSM4T(b1f[nt], bK + B_SPLIT_B + nt * 32);
#pragma unroll
            for (int ti = 0; ti < 2; ti++)
#pragma unroll
                for (int nj = 0; nj < 4; nj++)
                    MMA16816(acc[ti][nj], a0f[ti], b0f[nj >> 1][(nj & 1) * 2], b0f[nj >> 1][(nj & 1) * 2 + 1]);
#pragma unroll
            for (int ti = 0; ti < 2; ti++)
#pragma unroll
                for (int nj = 0; nj < 4; nj++)
                    MMA16816(acc[ti][nj], a1f[ti], b0f[nj >> 1][(nj & 1) * 2], b0f[nj >> 1][(nj & 1) * 2 + 1]);
#pragma unroll
            for (int ti = 0; ti < 2; ti++)
#pragma unroll
                for (int nj = 0; nj < 4; nj++)
                    MMA16816(acc[ti][nj], a0f[ti], b1f[nj >> 1][(nj & 1) * 2], b1f[nj >> 1][(nj & 1) * 2 + 1]);
        }
        stg = (stg == STAGES - 1) ? 0 : stg + 1;
    }

    // ---- epilogue: bias+relu, then fused router/importance partials ----
    const bool isH1 = (n0 < HD);
    const int nadj = isH1 ? n0 : (n0 - HD);
    const float* bias = isH1 ? b1 : bi1;
    const int lgrp = lane & 3;
#pragma unroll
    for (int ti = 0; ti < 2; ti++) {
        const int rbase = m0 + mbase + ti * 16 + (lane >> 2);
#pragma unroll
        for (int half = 0; half < 2; half++) {
            const int row = rbase + half * 8;
            float h[8];
#pragma unroll
            for (int nj = 0; nj < 4; nj++) {
                int cn = nadj + nbase + nj * 8 + lgrp * 2;
                h[nj * 2]     = fmaxf(acc[ti][nj][half * 2]     + __ldg(bias + cn),     0.f);
                h[nj * 2 + 1] = fmaxf(acc[ti][nj][half * 2 + 1] + __ldg(bias + cn + 1), 0.f);
            }
            if (isH1) {
                float le[16];
#pragma unroll
                for (int e = 0; e < 16; e++) le[e] = 0.f;
#pragma unroll
                for (int nj = 0; nj < 4; nj++) {
#pragma unroll
                    for (int j = 0; j < 2; j++) {
                        int col = nadj + nbase + nj * 8 + lgrp * 2 + j;
                        float hv = h[nj * 2 + j];
                        const float4* w = (const float4*)(W2 + (size_t)col * NE);
                        float4 w0 = __ldg(w), w1 = __ldg(w + 1), w2v = __ldg(w + 2), w3 = __ldg(w + 3);
                        le[0]  += hv * w0.x;  le[1]  += hv * w0.y;  le[2]  += hv * w0.z;  le[3]  += hv * w0.w;
                        le[4]  += hv * w1.x;  le[5]  += hv * w1.y;  le[6]  += hv * w1.z;  le[7]  += hv * w1.w;
                        le[8]  += hv * w2v.x; le[9]  += hv * w2v.y; le[10] += hv * w2v.z; le[11] += hv * w2v.w;
                        le[12] += hv * w3.x;  le[13] += hv * w3.y;  le[14] += hv * w3.z;  le[15] += hv * w3.w;
                    }
                }
#pragma unroll
                for (int e = 0; e < 16; e++) {
                    le[e] += __shfl_xor_sync(0xffffffffu, le[e], 1);
                    le[e] += __shfl_xor_sync(0xffffffffu, le[e], 2);
                }
                if (lgrp == 0) {
#pragma unroll
                    for (int e = 0; e < 16; e++)
                        atomicAdd(&g_logits[(size_t)row * NE + e], le[e]);
                }
            } else {
                float s = 0.f;
#pragma unroll
                for (int nj = 0; nj < 4; nj++) {
#pragma unroll
                    for (int j = 0; j < 2; j++) {
                        int col = nadj + nbase + nj * 8 + lgrp * 2 + j;
                        s += h[nj * 2 + j] * __ldg(&Wi2[col]);
                    }
                }
                s += __shfl_xor_sync(0xffffffffu, s, 1);
                s += __shfl_xor_sync(0xffffffffu, s, 2);
                if (lgrp == 0) atomicAdd(&g_impacc[row], s);
            }
        }
    }
}

// ===========================================================================
// conv_all: fp32->bf16 split of X and [W1|Wi1], plus accumulator init.
// ===========================================================================
__device__ __forceinline__ void split_bf16(float f, __nv_bfloat16& h0, __nv_bfloat16& h1) {
    h0 = __float2bfloat16_rn(f);
    h1 = __float2bfloat16_rn(f - __bfloat162float(h0));
}

__global__ __launch_bounds__(256)
void conv_all(const float* __restrict__ X, const float* __restrict__ W1,
              const float* __restrict__ Wi1) {
    const int b = blockIdx.x;
    const int t = threadIdx.x;
    if (b < 4096) {
        size_t i = (size_t)b * 256 + t;
        float4 v = ((const float4*)X)[i];
        __nv_bfloat162 a0, a1, b0, b1;
        split_bf16(v.x, a0.x, a1.x); split_bf16(v.y, a0.y, a1.y);
        split_bf16(v.z, b0.x, b1.x); split_bf16(v.w, b0.y, b1.y);
        ((__nv_bfloat162*)g_A0)[2 * i]     = a0;
        ((__nv_bfloat162*)g_A0)[2 * i + 1] = b0;
        ((__nv_bfloat162*)g_A1)[2 * i]     = a1;
        ((__nv_bfloat162*)g_A1)[2 * i + 1] = b1;
    } else if (b < 5632) {
        size_t i = (size_t)(b - 4096) * 256 + t;
        int r = (int)(i / 384);
        int c = (int)(i % 384) * 4;
        float4 v = (c < HD) ? *(const float4*)(W1 + (size_t)r * HD + c)
                            : *(const float4*)(Wi1 + (size_t)r * HI2 + c - HD);
        __nv_bfloat162 a0, a1, b0, b1;
        split_bf16(v.x, a0.x, a1.x); split_bf16(v.y, a0.y, a1.y);
        split_bf16(v.z, b0.x, b1.x); split_bf16(v.w, b0.y, b1.y);
        ((__nv_bfloat162*)g_B0)[2 * i]     = a0;
        ((__nv_bfloat162*)g_B0)[2 * i + 1] = b0;
        ((__nv_bfloat162*)g_B1)[2 * i]     = a1;
        ((__nv_bfloat162*)g_B1)[2 * i + 1] = b1;
    } else if (b < 5696) {
        size_t i = (size_t)(b - 5632) * 256 + t;   // 16384 float4 = 65536 floats
        ((float4*)g_logits)[i] = make_float4(0.f, 0.f, 0.f, 0.f);
    } else {
        for (int i = t; i < BSZ; i += 256) g_impacc[i] = 0.f;
        for (int i = t; i < HD; i += 256) g_avg[i] = 0.f;
        if (t < NE) g_probsum[t] = 0.f;
        if (t == 0) { g_impsum = 0.f; g_aux = 0.f; }
        if (t < 2) g_tkl[t] = 0.f;
        if (t < 4) g_bar[t] = 0;
    }
}

// ===========================================================================
// zero_col: blocks 0..2047 zero dispatch+combine (streaming stores);
//           blocks 2048..2111 column-sum X into g_avg
// ===========================================================================
__global__ __launch_bounds__(256)
void zero_col(float* __restrict__ out, const float* __restrict__ X) {
    const int b = blockIdx.x;
    const int t = threadIdx.x;
    if (b < 2048) {
        long long stride = 2048LL * 256;
        long long i = (long long)b * 256 + t;
        long long n4 = (2 * D_SZ) >> 2;
        float4 z = make_float4(0.f, 0.f, 0.f, 0.f);
        for (long long j = i; j < n4; j += stride)
            __stcs(&((float4*)out)[j], z);
    } else {
        int r0 = (b - 2048) * 64;
        float4 s = make_float4(0.f, 0.f, 0.f, 0.f);
        for (int r = r0; r < r0 + 64; r++) {
            float4 v = ((const float4*)X)[(size_t)r * 256 + t];
            s.x += v.x; s.y += v.y; s.z += v.z; s.w += v.w;
        }
        atomicAdd(&g_avg[t * 4 + 0], s.x);
        atomicAdd(&g_avg[t * 4 + 1], s.y);
        atomicAdd(&g_avg[t * 4 + 2], s.z);
        atomicAdd(&g_avg[t * 4 + 3], s.w);
    }
}

// ===========================================================================
// tail kernel: softmax+top2+imp -> bar -> tk matvec -> bar -> scan -> bar -> aux
// grid = 64 blocks x 256 threads (all co-resident; spin barriers).
// ===========================================================================
#define TAIL_BLOCKS 64

__device__ __forceinline__ void grid_bar(int id) {
    __syncthreads();
    if (threadIdx.x == 0) {
        __threadfence();
        atomicAdd(&g_bar[id], 1);
        while (*(volatile int*)&g_bar[id] < TAIL_BLOCKS) { }
    }
    __syncthreads();
}

__global__ __launch_bounds__(256)
void tail_kernel(const float* __restrict__ b2, const float* __restrict__ bi2,
                 const float* __restrict__ Wt1, const float* __restrict__ bt1,
                 const float* __restrict__ Wt2, const float* __restrict__ bt2,
                 float* __restrict__ out) {
    const int blk = blockIdx.x;
    const int t = threadIdx.x;
    const int lane = t & 31;
    __shared__ float sred[256 * 4];

    // ---------------- P1: softmax + top2 + probsum + importance ----------------
    {
        const int token = blk * 64 + (t & 63);          // 64 tokens/block, x4 redundancy? no:
        // use only first 64 threads' tokens... instead: gid mapping
    }
    {
        const int gid = blk * 256 + t;
        if (gid < BSZ) {
            const int token = gid;
            float p[NE];
            const float4* lg = (const float4*)(g_logits + (size_t)token * NE);
#pragma unroll
            for (int q = 0; q < 4; q++) {
                float4 v = lg[q];
                p[q * 4 + 0] = v.x + b2[q * 4 + 0];
                p[q * 4 + 1] = v.y + b2[q * 4 + 1];
                p[q * 4 + 2] = v.z + b2[q * 4 + 2];
                p[q * 4 + 3] = v.w + b2[q * 4 + 3];
            }
            float mx = -1e30f;
#pragma unroll
            for (int e = 0; e < NE; e++) mx = fmaxf(mx, p[e]);
            float sum = 0.f;
#pragma unroll
            for (int e = 0; e < NE; e++) { p[e] = expf(p[e] - mx); sum += p[e]; }
            float inv = 1.f / sum;
#pragma unroll
            for (int e = 0; e < NE; e++) p[e] *= inv;

            float4* rp = (float4*)(out + RP_OFF + (size_t)token * NE);
#pragma unroll
            for (int q = 0; q < 4; q++)
                rp[q] = make_float4(p[q * 4], p[q * 4 + 1], p[q * 4 + 2], p[q * 4 + 3]);

            int e0 = 0;
#pragma unroll
            for (int e = 1; e < NE; e++) if (p[e] > p[e0]) e0 = e;
            int best = -1; float bv = -1.f;
#pragma unroll
            for (int e = 0; e < NE; e++) {
                if (e == e0) continue;
                if (p[e] > bv) { bv = p[e]; best = e; }
            }
            g_tp[token * 2 + 0] = p[e0];
            g_tp[token * 2 + 1] = p[best];
            g_te[token * 2 + 0] = e0;
            g_te[token * 2 + 1] = best;

#pragma unroll
            for (int e = 0; e < NE; e++) {
                float v = p[e];
#pragma unroll
                for (int o = 16; o; o >>= 1) v += __shfl_xor_sync(0xffffffffu, v, o);
                if (lane == 0) atomicAdd(&g_probsum[e], v);
            }

            float im = 1.f / (1.f + expf(-(g_impacc[token] + bi2[0])));
            out[IMP_OFF + token] = im;
            float vs = im;
#pragma unroll
            for (int o = 16; o; o >>= 1) vs += __shfl_xor_sync(0xffffffffu, vs, o);
            if (lane == 0) atomicAdd(&g_impsum, vs);
        }
    }
    grid_bar(0);

    // ---------------- P2: top-k predictor matvec (units 4*blk .. 4*blk+3) -----
    {
        const float invN = 1.f / 4096.f;
        const int j0 = blk * 4;
        float4 a4 = make_float4(0.f, 0.f, 0.f, 0.f);
        for (int i = t; i < HD; i += 256) {
            float av = g_avg[i] * invN;
            float4 w = *(const float4*)&Wt1[(size_t)i * 256 + j0];
            a4.x += av * w.x; a4.y += av * w.y; a4.z += av * w.z; a4.w += av * w.w;
        }
        sred[t * 4 + 0] = a4.x;
        sred[t * 4 + 1] = a4.y;
        sred[t * 4 + 2] = a4.z;
        sred[t * 4 + 3] = a4.w;
        __syncthreads();
        for (int o = 128; o; o >>= 1) {
            if (t < o) {
#pragma unroll
                for (int c = 0; c < 4; c++)
                    sred[t * 4 + c] += sred[(t + o) * 4 + c];
            }
            __syncthreads();
        }
        if (t < 4) {
            int j = j0 + t;
            float a = sred[t] + (g_impsum * invN) * Wt1[(size_t)HD * 256 + j] + bt1[j];
            float h = fmaxf(a, 0.f);
            atomicAdd(&g_tkl[0], h * Wt2[j * 2 + 0]);
            atomicAdd(&g_tkl[1], h * Wt2[j * 2 + 1]);
            if (j == 0) {
                atomicAdd(&g_tkl[0], bt2[0]);
                atomicAdd(&g_tkl[1], bt2[1]);
            }
        }
    }
    grid_bar(1);

    // ---------------- P3: per-expert scan + scatter (blocks 0..15) ------------
    if (blk < NE) {
        int* cnt = (int*)sred;
        const int e = blk;
        const int k = (g_tkl[1] > g_tkl[0]) ? 2 : 1;
        const int cap = 384 * k;
        const int base = t * 32;

        int local = 0;
#pragma unroll 4
        for (int i = 0; i < 32; i++) {
            int n = base + i;
            if ((n & 1) < k && g_te[n] == e) local++;
        }
        cnt[t] = local;
        __syncthreads();
        for (int off = 1; off < 256; off <<= 1) {
            int v = (t >= off) ? cnt[t - off] : 0;
            __syncthreads();
            cnt[t] += v;
            __syncthreads();
        }
        int total = cnt[255];
        int pos = cnt[t] - local;   // exclusive prefix

        float* disp = out;
        float* comb = out + COMB_OFF;
        const float* imp = out + IMP_OFF;

        for (int i = 0; i < 32; i++) {
            int n = base + i;
            int slot = n & 1;
            if (slot >= k || g_te[n] != e) continue;
            if (pos < cap) {
                int token = n >> 1;
                float tp0 = g_tp[token * 2 + 0];
                float tp1 = g_tp[token * 2 + 1];
                float denom = (k == 2) ? (tp0 + tp1 + 1e-8f) : (tp0 + 1e-8f);
                float pn = ((slot == 0) ? tp0 : tp1) / denom;
                float f = 1.f + ((imp[token] > 0.5f) ? 1.f : 0.f);
                long long off = (long long)token * NE * CAPM + (long long)e * CAPM + pos;
                disp[off] = 1.f;
                comb[off] = pn * f;
            }
            pos++;
        }
        if (t == 0) {
            float invN = 1.f / 4096.f;
            float invA = 1.f / (4096.f * (float)k);
            atomicAdd(&g_aux, (g_probsum[e] * invN) * ((float)total * invA) * (float)NE);
        }
    }
    grid_bar(2);

    if (blk == 0 && t == 0)
        out[AUX_OFF] = g_aux;
}

// ---------------------------------------------------------------------------
extern "C" void kernel_launch(void* const* d_in, const int* in_sizes, int n_in,
                              void* d_out, int out_size) {
    const float* X   = (const float*)d_in[0];
    const float* W1  = (const float*)d_in[1];
    const float* b1  = (const float*)d_in[2];
    const float* W2  = (const float*)d_in[3];
    const float* b2  = (const float*)d_in[4];
    const float* Wi1 = (const float*)d_in[5];
    const float* bi1 = (const float*)d_in[6];
    const float* Wi2 = (const float*)d_in[7];
    const float* bi2 = (const float*)d_in[8];
    const float* Wt1 = (const float*)d_in[9];
    const float* bt1 = (const float*)d_in[10];
    const float* Wt2 = (const float*)d_in[11];
    const float* bt2 = (const float*)d_in[12];
    float* out = (float*)d_out;

    __nv_bfloat16 *A0p = nullptr, *A1p = nullptr, *B0p = nullptr, *B1p = nullptr;
    cudaGetSymbolAddress((void**)&A0p, g_A0);
    cudaGetSymbolAddress((void**)&A1p, g_A1);
    cudaGetSymbolAddress((void**)&B0p, g_B0);
    cudaGetSymbolAddress((void**)&B1p, g_B1);

    cudaFuncSetAttribute(gemm_mma, cudaFuncAttributeMaxDynamicSharedMemorySize, SMEMT);

    static cudaStream_t s1 = nullptr;
    static cudaEvent_t evF = nullptr, ev1 = nullptr;
    if (!s1) {
        cudaStreamCreateWithFlags(&s1, cudaStreamNonBlocking);
        cudaEventCreateWithFlags(&evF, cudaEventDisableTiming);
        cudaEventCreateWithFlags(&ev1, cudaEventDisableTiming);
    }

    // 1) conversions + all accumulator/barrier init
    conv_all<<<5697, 256>>>(X, W1, Wi1);
    cudaEventRecord(evF, 0);

    // 2) GEMM with fused router/importance epilogue (main stream)
    gemm_mma<<<dim3(NT / 128, BSZ / 64), 256, SMEMT>>>(A0p, A1p, B0p, B1p,
                                                       b1, bi1, W2, Wi2);

    // 3) side stream: zero-fill + colmean, hidden under the GEMM window
    cudaStreamWaitEvent(s1, evF, 0);
    zero_col<<<2112, 256, 0, s1>>>(out, X);
    cudaEventRecord(ev1, s1);

    // 4) single fused tail: softmax/top2/imp -> tk -> scan -> aux
    cudaStreamWaitEvent(0, ev1, 0);
    tail_kernel<<<TAIL_BLOCKS, 256>>>(b2, bi2, Wt1, bt1, Wt2, bt2, out);
}

// round 13
// speedup vs baseline: 1.0302x; 1.0302x over previous
#include <cuda_runtime.h>
#include <cuda_bf16.h>
#include <math.h>
#include <cstdint>

// Problem constants
#define BSZ   4096        // B*S tokens
#define HD    1024        // hidden
#define NE    16          // experts
#define CAPM  768         // CAP_MAX
#define HI2   512         // H/2
#define NT    1536        // combined N (W1 | Wi1)

static const long long D_SZ    = (long long)BSZ * NE * CAPM;       // 50331648
static const long long COMB_OFF= D_SZ;
static const long long RP_OFF  = 2 * D_SZ;                         // 100663296
static const long long AUX_OFF = RP_OFF + (long long)BSZ * NE;     // 100728832
static const long long IMP_OFF = AUX_OFF + 1;                      // 100728833

// Scratch (device globals; no cudaMalloc allowed)
__device__ __nv_bfloat16 g_A0[(size_t)BSZ * HD];   // bf16 hi split of X
__device__ __nv_bfloat16 g_A1[(size_t)BSZ * HD];   // bf16 lo split of X
__device__ __nv_bfloat16 g_B0[(size_t)HD * NT];    // bf16 hi split of [W1|Wi1]
__device__ __nv_bfloat16 g_B1[(size_t)HD * NT];    // bf16 lo split
__device__ float g_logits[(size_t)BSZ * NE];       // router logits accumulator
__device__ float g_impacc[BSZ];                    // importance pre-sigmoid accumulator
__device__ float g_avg[HD];                  // column sums of X
__device__ float g_impsum;                   // sum of importance
__device__ float g_probsum[NE];              // sum of router probs per expert
__device__ float g_tkl[2];                   // top-k predictor logits
__device__ float g_tp[BSZ * 2];              // top-2 probs
__device__ int   g_te[BSZ * 2];              // top-2 expert ids

// ===========================================================================
// PTX helpers (portable; nothing sm_103a-suffix-gated)
// ===========================================================================
__device__ __forceinline__ uint32_t smem_to_u32(const void* p) {
    uint32_t a;
    asm("{ .reg .u64 t; cvta.to.shared.u64 t, %1; cvt.u32.u64 %0, t; }" : "=r"(a) : "l"(p));
    return a;
}
#define LDSM4(d, a) \
    asm volatile("ldmatrix.sync.aligned.m8n8.x4.shared.b16 {%0,%1,%2,%3}, [%4];" \
        : "=r"((d)[0]), "=r"((d)[1]), "=r"((d)[2]), "=r"((d)[3]) : "r"(a))
#define LDSM4T(d, a) \
    asm volatile("ldmatrix.sync.aligned.m8n8.x4.trans.shared.b16 {%0,%1,%2,%3}, [%4];" \
        : "=r"((d)[0]), "=r"((d)[1]), "=r"((d)[2]), "=r"((d)[3]) : "r"(a))
#define MMA16816(c, a, b0, b1) \
    asm volatile("mma.sync.aligned.m16n8k16.row.col.f32.bf16.bf16.f32 " \
        "{%0,%1,%2,%3}, {%4,%5,%6,%7}, {%8,%9}, {%0,%1,%2,%3};" \
        : "+f"((c)[0]), "+f"((c)[1]), "+f"((c)[2]), "+f"((c)[3]) \
        : "r"((a)[0]), "r"((a)[1]), "r"((a)[2]), "r"((a)[3]), "r"(b0), "r"(b1))
#define CP16(s, g) \
    asm volatile("cp.async.cg.shared.global [%0], [%1], 16;" :: "r"(s), "l"(g))
#define CP_COMMIT() asm volatile("cp.async.commit_group;" ::: "memory")
#define CP_WAIT1()  asm volatile("cp.async.wait_group 1;" ::: "memory")
#define CP_WAIT0()  asm volatile("cp.async.wait_group 0;" ::: "memory")

// smem geometry (bytes): padded rows for conflict-free ldmatrix
#define AS_ROWB   80                     // 32 bf16 + pad -> 80B rows
#define BS_ROWB   272                    // 128 bf16 + pad -> 272B rows
#define A_SPLIT_B (64 * AS_ROWB)         // 5120
#define B_SPLIT_B (32 * BS_ROWB)         // 8704
#define B_OFF     (2 * A_SPLIT_B)        // 10240
#define BUF_B     (B_OFF + 2 * B_SPLIT_B)// 27648
#define STAGES    3
#define SMEMT     (STAGES * BUF_B)       // 82944

// ===========================================================================
// fused HMMA bf16-split GEMM with router/importance epilogue (R11, proven)
// ===========================================================================
__global__ __launch_bounds__(256, 2)
void gemm_mma(const __nv_bfloat16* __restrict__ A0g, const __nv_bfloat16* __restrict__ A1g,
              const __nv_bfloat16* __restrict__ B0g, const __nv_bfloat16* __restrict__ B1g,
              const float* __restrict__ b1, const float* __restrict__ bi1,
              const float* __restrict__ W2, const float* __restrict__ Wi2) {
    extern __shared__ char smem[];
    const uint32_t sb = smem_to_u32(smem);
    const int tid = threadIdx.x, wid = tid >> 5, lane = tid & 31;
    const int m0 = blockIdx.y * 64;
    const int n0 = blockIdx.x * 128;

    const int ar = tid >> 2, acq = tid & 3;
    const int br = tid >> 3, bcq = tid & 7;
    const __nv_bfloat16* A0p = A0g + (size_t)(m0 + ar) * HD + acq * 8;
    const __nv_bfloat16* A1p = A1g + (size_t)(m0 + ar) * HD + acq * 8;
    const __nv_bfloat16* B0p = B0g + (size_t)br * NT + n0 + bcq * 16;
    const __nv_bfloat16* B1p = B1g + (size_t)br * NT + n0 + bcq * 16;
    const uint32_t asw = sb + (uint32_t)ar * AS_ROWB + acq * 16;
    const uint32_t bsw = sb + B_OFF + (uint32_t)br * BS_ROWB + bcq * 32;

    auto issue = [&](int it, int stg) {
        const uint32_t a = asw + stg * BUF_B;
        CP16(a,             A0p + it * 32);
        CP16(a + A_SPLIT_B, A1p + it * 32);
        const uint32_t b = bsw + stg * BUF_B;
        const __nv_bfloat16* pb0 = B0p + (size_t)it * 32 * NT;
        const __nv_bfloat16* pb1 = B1p + (size_t)it * 32 * NT;
        CP16(b,                  pb0);
        CP16(b + 16,             pb0 + 8);
        CP16(b + B_SPLIT_B,      pb1);
        CP16(b + B_SPLIT_B + 16, pb1 + 8);
        CP_COMMIT();
    };

    const int wm = wid >> 2, wn = wid & 3;
    const int mbase = wm * 32, nbase = wn * 32;
    const int l8 = lane & 7, lb8 = (lane >> 3) & 1, lhi = lane >> 4;
    const uint32_t aAddr = sb + (uint32_t)(mbase + l8 + 8 * lb8) * AS_ROWB + lhi * 16;
    const uint32_t bAddr = sb + B_OFF + (uint32_t)(l8 + 8 * lb8) * BS_ROWB
                         + (uint32_t)(nbase + lhi * 8) * 2;

    float acc[2][4][4];
#pragma unroll
    for (int i = 0; i < 2; i++)
#pragma unroll
        for (int j = 0; j < 4; j++)
#pragma unroll
            for (int c = 0; c < 4; c++) acc[i][j][c] = 0.f;

    issue(0, 0);
    issue(1, 1);

    int stg = 0;
    for (int it = 0; it < 32; it++) {
        if (it < 30) CP_WAIT1(); else CP_WAIT0();
        __syncthreads();
        if (it < 30) issue(it + 2, (it + 2) % STAGES);

        const uint32_t aB = aAddr + stg * BUF_B;
        const uint32_t bB = bAddr + stg * BUF_B;
#pragma unroll
        for (int ks = 0; ks < 2; ks++) {
            const uint32_t aK = aB + ks * 32;
            const uint32_t bK = bB + ks * 16 * BS_ROWB;
            uint32_t a0f[2][4], a1f[2][4], b0f[2][4], b1f[2][4];
#pragma unroll
            for (int nt = 0; nt < 2; nt++) LDSM4T(b0f[nt], bK + nt * 32);
#pragma unroll
            for (int ti = 0; ti < 2; ti++) LDSM4(a0f[ti], aK + ti * 16 * AS_ROWB);
#pragma unroll
            for (int ti = 0; ti < 2; ti++) LDSM4(a1f[ti], aK + A_SPLIT_B + ti * 16 * AS_ROWB);
#pragma unroll
            for (int nt = 0; nt < 2; nt++) LDSM4T(b1f[nt], bK + B_SPLIT_B + nt * 32);
#pragma unroll
            for (int ti = 0; ti < 2; ti++)
#pragma unroll
                for (int nj = 0; nj < 4; nj++)
                    MMA16816(acc[ti][nj], a0f[ti], b0f[nj >> 1][(nj & 1) * 2], b0f[nj >> 1][(nj & 1) * 2 + 1]);
#pragma unroll
            for (int ti = 0; ti < 2; ti++)
#pragma unroll
                for (int nj = 0; nj < 4; nj++)
                    MMA16816(acc[ti][nj], a1f[ti], b0f[nj >> 1][(nj & 1) * 2], b0f[nj >> 1][(nj & 1) * 2 + 1]);
#pragma unroll
            for (int ti = 0; ti < 2; ti++)
#pragma unroll
                for (int nj = 0; nj < 4; nj++)
                    MMA16816(acc[ti][nj], a0f[ti], b1f[nj >> 1][(nj & 1) * 2], b1f[nj >> 1][(nj & 1) * 2 + 1]);
        }
        stg = (stg == STAGES - 1) ? 0 : stg + 1;
    }

    // ---- epilogue: bias+relu, then fused router/importance partials ----
    const bool isH1 = (n0 < HD);
    const int nadj = isH1 ? n0 : (n0 - HD);
    const float* bias = isH1 ? b1 : bi1;
    const int lgrp = lane & 3;
#pragma unroll
    for (int ti = 0; ti < 2; ti++) {
        const int rbase = m0 + mbase + ti * 16 + (lane >> 2);
#pragma unroll
        for (int half = 0; half < 2; half++) {
            const int row = rbase + half * 8;
            float h[8];
#pragma unroll
            for (int nj = 0; nj < 4; nj++) {
                int cn = nadj + nbase + nj * 8 + lgrp * 2;
                h[nj * 2]     = fmaxf(acc[ti][nj][half * 2]     + __ldg(bias + cn),     0.f);
                h[nj * 2 + 1] = fmaxf(acc[ti][nj][half * 2 + 1] + __ldg(bias + cn + 1), 0.f);
            }
            if (isH1) {
                float le[16];
#pragma unroll
                for (int e = 0; e < 16; e++) le[e] = 0.f;
#pragma unroll
                for (int nj = 0; nj < 4; nj++) {
#pragma unroll
                    for (int j = 0; j < 2; j++) {
                        int col = nadj + nbase + nj * 8 + lgrp * 2 + j;
                        float hv = h[nj * 2 + j];
                        const float4* w = (const float4*)(W2 + (size_t)col * NE);
                        float4 w0 = __ldg(w), w1 = __ldg(w + 1), w2v = __ldg(w + 2), w3 = __ldg(w + 3);
                        le[0]  += hv * w0.x;  le[1]  += hv * w0.y;  le[2]  += hv * w0.z;  le[3]  += hv * w0.w;
                        le[4]  += hv * w1.x;  le[5]  += hv * w1.y;  le[6]  += hv * w1.z;  le[7]  += hv * w1.w;
                        le[8]  += hv * w2v.x; le[9]  += hv * w2v.y; le[10] += hv * w2v.z; le[11] += hv * w2v.w;
                        le[12] += hv * w3.x;  le[13] += hv * w3.y;  le[14] += hv * w3.z;  le[15] += hv * w3.w;
                    }
                }
#pragma unroll
                for (int e = 0; e < 16; e++) {
                    le[e] += __shfl_xor_sync(0xffffffffu, le[e], 1);
                    le[e] += __shfl_xor_sync(0xffffffffu, le[e], 2);
                }
                if (lgrp == 0) {
#pragma unroll
                    for (int e = 0; e < 16; e++)
                        atomicAdd(&g_logits[(size_t)row * NE + e], le[e]);
                }
            } else {
                float s = 0.f;
#pragma unroll
                for (int nj = 0; nj < 4; nj++) {
#pragma unroll
                    for (int j = 0; j < 2; j++) {
                        int col = nadj + nbase + nj * 8 + lgrp * 2 + j;
                        s += h[nj * 2 + j] * __ldg(&Wi2[col]);
                    }
                }
                s += __shfl_xor_sync(0xffffffffu, s, 1);
                s += __shfl_xor_sync(0xffffffffu, s, 2);
                if (lgrp == 0) atomicAdd(&g_impacc[row], s);
            }
        }
    }
}

// ===========================================================================
// conv_all: fp32->bf16 split of X and [W1|Wi1], plus accumulator init.
// blocks 0..4095 = A, 4096..5631 = B, 5632..5695 = zero g_logits, 5696 = rest
// ===========================================================================
__device__ __forceinline__ void split_bf16(float f, __nv_bfloat16& h0, __nv_bfloat16& h1) {
    h0 = __float2bfloat16_rn(f);
    h1 = __float2bfloat16_rn(f - __bfloat162float(h0));
}

__global__ __launch_bounds__(256)
void conv_all(const float* __restrict__ X, const float* __restrict__ W1,
              const float* __restrict__ Wi1, float* __restrict__ out) {
    const int b = blockIdx.x;
    const int t = threadIdx.x;
    if (b < 4096) {
        size_t i = (size_t)b * 256 + t;
        float4 v = ((const float4*)X)[i];
        __nv_bfloat162 a0, a1, b0, b1;
        split_bf16(v.x, a0.x, a1.x); split_bf16(v.y, a0.y, a1.y);
        split_bf16(v.z, b0.x, b1.x); split_bf16(v.w, b0.y, b1.y);
        ((__nv_bfloat162*)g_A0)[2 * i]     = a0;
        ((__nv_bfloat162*)g_A0)[2 * i + 1] = b0;
        ((__nv_bfloat162*)g_A1)[2 * i]     = a1;
        ((__nv_bfloat162*)g_A1)[2 * i + 1] = b1;
    } else if (b < 5632) {
        size_t i = (size_t)(b - 4096) * 256 + t;
        int r = (int)(i / 384);
        int c = (int)(i % 384) * 4;
        float4 v = (c < HD) ? *(const float4*)(W1 + (size_t)r * HD + c)
                            : *(const float4*)(Wi1 + (size_t)r * HI2 + c - HD);
        __nv_bfloat162 a0, a1, b0, b1;
        split_bf16(v.x, a0.x, a1.x); split_bf16(v.y, a0.y, a1.y);
        split_bf16(v.z, b0.x, b1.x); split_bf16(v.w, b0.y, b1.y);
        ((__nv_bfloat162*)g_B0)[2 * i]     = a0;
        ((__nv_bfloat162*)g_B0)[2 * i + 1] = b0;
        ((__nv_bfloat162*)g_B1)[2 * i]     = a1;
        ((__nv_bfloat162*)g_B1)[2 * i + 1] = b1;
    } else if (b < 5696) {
        size_t i = (size_t)(b - 5632) * 256 + t;   // 16384 float4 = 65536 floats
        ((float4*)g_logits)[i] = make_float4(0.f, 0.f, 0.f, 0.f);
    } else {
        for (int i = t; i < BSZ; i += 256) g_impacc[i] = 0.f;
        for (int i = t; i < HD; i += 256) g_avg[i] = 0.f;
        if (t < NE) g_probsum[t] = 0.f;
        if (t == 0) { g_impsum = 0.f; out[AUX_OFF] = 0.f; }
        if (t < 2) g_tkl[t] = 0.f;
    }
}

// ===========================================================================
// zero_col: blocks 0..2047 zero dispatch+combine (streaming stores);
//           blocks 2048..2111 column-sum X into g_avg
// ===========================================================================
__global__ __launch_bounds__(256)
void zero_col(float* __restrict__ out, const float* __restrict__ X) {
    const int b = blockIdx.x;
    const int t = threadIdx.x;
    if (b < 2048) {
        long long stride = 2048LL * 256;
        long long i = (long long)b * 256 + t;
        long long n4 = (2 * D_SZ) >> 2;
        float4 z = make_float4(0.f, 0.f, 0.f, 0.f);
        for (long long j = i; j < n4; j += stride)
            __stcs(&((float4*)out)[j], z);
    } else {
        int r0 = (b - 2048) * 64;
        float4 s = make_float4(0.f, 0.f, 0.f, 0.f);
        for (int r = r0; r < r0 + 64; r++) {
            float4 v = ((const float4*)X)[(size_t)r * 256 + t];
            s.x += v.x; s.y += v.y; s.z += v.z; s.w += v.w;
        }
        atomicAdd(&g_avg[t * 4 + 0], s.x);
        atomicAdd(&g_avg[t * 4 + 1], s.y);
        atomicAdd(&g_avg[t * 4 + 2], s.z);
        atomicAdd(&g_avg[t * 4 + 3], s.w);
    }
}

// ===========================================================================
// softmax_top2: one thread per token. grid 64 x 256 (wide for latency).
// ===========================================================================
__global__ __launch_bounds__(256)
void softmax_top2(const float* __restrict__ b2, const float* __restrict__ bi2,
                  float* __restrict__ out) {
    const int token = blockIdx.x * 64 + (threadIdx.x & 63) + (threadIdx.x >> 6) * 4096;
    // simpler: 64 blocks x 256 threads = 16384 > 4096; mask
    const int gid = blockIdx.x * 256 + threadIdx.x;
    const int lane = threadIdx.x & 31;
    (void)token;
    if (gid >= BSZ) return;
    const int tok = gid;

    float p[NE];
    const float4* lg = (const float4*)(g_logits + (size_t)tok * NE);
#pragma unroll
    for (int q = 0; q < 4; q++) {
        float4 v = lg[q];
        p[q * 4 + 0] = v.x + b2[q * 4 + 0];
        p[q * 4 + 1] = v.y + b2[q * 4 + 1];
        p[q * 4 + 2] = v.z + b2[q * 4 + 2];
        p[q * 4 + 3] = v.w + b2[q * 4 + 3];
    }
    float mx = -1e30f;
#pragma unroll
    for (int e = 0; e < NE; e++) mx = fmaxf(mx, p[e]);
    float sum = 0.f;
#pragma unroll
    for (int e = 0; e < NE; e++) { p[e] = expf(p[e] - mx); sum += p[e]; }
    float inv = 1.f / sum;
#pragma unroll
    for (int e = 0; e < NE; e++) p[e] *= inv;

    float4* rp = (float4*)(out + RP_OFF + (size_t)tok * NE);
#pragma unroll
    for (int q = 0; q < 4; q++)
        rp[q] = make_float4(p[q * 4], p[q * 4 + 1], p[q * 4 + 2], p[q * 4 + 3]);

    int e0 = 0;
#pragma unroll
    for (int e = 1; e < NE; e++) if (p[e] > p[e0]) e0 = e;
    int best = -1; float bv = -1.f;
#pragma unroll
    for (int e = 0; e < NE; e++) {
        if (e == e0) continue;
        if (p[e] > bv) { bv = p[e]; best = e; }
    }
    g_tp[tok * 2 + 0] = p[e0];
    g_tp[tok * 2 + 1] = p[best];
    g_te[tok * 2 + 0] = e0;
    g_te[tok * 2 + 1] = best;

#pragma unroll
    for (int e = 0; e < NE; e++) {
        float v = p[e];
#pragma unroll
        for (int o = 16; o; o >>= 1) v += __shfl_xor_sync(0xffffffffu, v, o);
        if (lane == 0) atomicAdd(&g_probsum[e], v);
    }

    float im = 1.f / (1.f + expf(-(g_impacc[tok] + bi2[0])));
    out[IMP_OFF + tok] = im;
    float vs = im;
#pragma unroll
    for (int o = 16; o; o >>= 1) vs += __shfl_xor_sync(0xffffffffu, vs, o);
    if (lane == 0) atomicAdd(&g_impsum, vs);
}

// ===========================================================================
// top-k predictor matvec: 64 blocks, block b computes units 4b..4b+3 (float4)
// ===========================================================================
__global__ __launch_bounds__(256)
void tk_matvec_kernel(const float* __restrict__ Wt1, const float* __restrict__ bt1,
                      const float* __restrict__ Wt2, const float* __restrict__ bt2) {
    const int j0 = blockIdx.x * 4;
    const int t = threadIdx.x;
    const float invN = 1.f / 4096.f;
    __shared__ float sred[256 * 4];

    float4 a4 = make_float4(0.f, 0.f, 0.f, 0.f);
    for (int i = t; i < HD; i += 256) {
        float av = g_avg[i] * invN;
        float4 w = *(const float4*)&Wt1[(size_t)i * 256 + j0];
        a4.x += av * w.x; a4.y += av * w.y; a4.z += av * w.z; a4.w += av * w.w;
    }
    sred[t * 4 + 0] = a4.x;
    sred[t * 4 + 1] = a4.y;
    sred[t * 4 + 2] = a4.z;
    sred[t * 4 + 3] = a4.w;
    __syncthreads();
    for (int o = 128; o; o >>= 1) {
        if (t < o) {
#pragma unroll
            for (int c = 0; c < 4; c++)
                sred[t * 4 + c] += sred[(t + o) * 4 + c];
        }
        __syncthreads();
    }
    if (t < 4) {
        int j = j0 + t;
        float a = sred[t] + (g_impsum * invN) * Wt1[(size_t)HD * 256 + j] + bt1[j];
        float h = fmaxf(a, 0.f);
        atomicAdd(&g_tkl[0], h * Wt2[j * 2 + 0]);
        atomicAdd(&g_tkl[1], h * Wt2[j * 2 + 1]);
        if (j == 0) {
            atomicAdd(&g_tkl[0], bt2[0]);
            atomicAdd(&g_tkl[1], bt2[1]);
        }
    }
}

// ===========================================================================
// per-expert parallel scan + scatter; aux added directly to out[AUX_OFF]
// ===========================================================================
__global__ __launch_bounds__(256)
void scan_scatter16_kernel(float* __restrict__ out) {
    const int e = blockIdx.x;
    const int t = threadIdx.x;
    const int k = (g_tkl[1] > g_tkl[0]) ? 2 : 1;
    const int cap = 384 * k;
    const int base = t * 32;

    __shared__ int cnt[256];
    int local = 0;
#pragma unroll 4
    for (int i = 0; i < 32; i++) {
        int n = base + i;
        if ((n & 1) < k && g_te[n] == e) local++;
    }
    cnt[t] = local;
    __syncthreads();
    for (int off = 1; off < 256; off <<= 1) {
        int v = (t >= off) ? cnt[t - off] : 0;
        __syncthreads();
        cnt[t] += v;
        __syncthreads();
    }
    int total = cnt[255];
    int pos = cnt[t] - local;   // exclusive prefix

    float* disp = out;
    float* comb = out + COMB_OFF;
    const float* imp = out + IMP_OFF;

    for (int i = 0; i < 32; i++) {
        int n = base + i;
        int slot = n & 1;
        if (slot >= k || g_te[n] != e) continue;
        if (pos < cap) {
            int token = n >> 1;
            float tp0 = g_tp[token * 2 + 0];
            float tp1 = g_tp[token * 2 + 1];
            float denom = (k == 2) ? (tp0 + tp1 + 1e-8f) : (tp0 + 1e-8f);
            float pn = ((slot == 0) ? tp0 : tp1) / denom;
            float f = 1.f + ((imp[token] > 0.5f) ? 1.f : 0.f);
            long long off = (long long)token * NE * CAPM + (long long)e * CAPM + pos;
            disp[off] = 1.f;
            comb[off] = pn * f;
        }
        pos++;
    }
    if (t == 0) {
        float invN = 1.f / 4096.f;
        float invA = 1.f / (4096.f * (float)k);
        atomicAdd(&out[AUX_OFF],
                  (g_probsum[e] * invN) * ((float)total * invA) * (float)NE);
    }
}

// ---------------------------------------------------------------------------
extern "C" void kernel_launch(void* const* d_in, const int* in_sizes, int n_in,
                              void* d_out, int out_size) {
    const float* X   = (const float*)d_in[0];
    const float* W1  = (const float*)d_in[1];
    const float* b1  = (const float*)d_in[2];
    const float* W2  = (const float*)d_in[3];
    const float* b2  = (const float*)d_in[4];
    const float* Wi1 = (const float*)d_in[5];
    const float* bi1 = (const float*)d_in[6];
    const float* Wi2 = (const float*)d_in[7];
    const float* bi2 = (const float*)d_in[8];
    const float* Wt1 = (const float*)d_in[9];
    const float* bt1 = (const float*)d_in[10];
    const float* Wt2 = (const float*)d_in[11];
    const float* bt2 = (const float*)d_in[12];
    float* out = (float*)d_out;

    __nv_bfloat16 *A0p = nullptr, *A1p = nullptr, *B0p = nullptr, *B1p = nullptr;
    cudaGetSymbolAddress((void**)&A0p, g_A0);
    cudaGetSymbolAddress((void**)&A1p, g_A1);
    cudaGetSymbolAddress((void**)&B0p, g_B0);
    cudaGetSymbolAddress((void**)&B1p, g_B1);

    cudaFuncSetAttribute(gemm_mma, cudaFuncAttributeMaxDynamicSharedMemorySize, SMEMT);

    static cudaStream_t s1 = nullptr;
    static cudaEvent_t evF = nullptr, ev1 = nullptr;
    if (!s1) {
        cudaStreamCreateWithFlags(&s1, cudaStreamNonBlocking);
        cudaEventCreateWithFlags(&evF, cudaEventDisableTiming);
        cudaEventCreateWithFlags(&ev1, cudaEventDisableTiming);
    }

    // 1) conversions + all accumulator init (incl. out[AUX_OFF] = 0)
    conv_all<<<5697, 256>>>(X, W1, Wi1, out);
    cudaEventRecord(evF, 0);

    // 2) GEMM with fused router/importance epilogue (main stream)
    gemm_mma<<<dim3(NT / 128, BSZ / 64), 256, SMEMT>>>(A0p, A1p, B0p, B1p,
                                                       b1, bi1, W2, Wi2);

    // 3) side stream: zero-fill + colmean, hidden under the GEMM window
    cudaStreamWaitEvent(s1, evF, 0);
    zero_col<<<2112, 256, 0, s1>>>(out, X);
    cudaEventRecord(ev1, s1);

    // 4) softmax + top2 + importance sigmoid (wide grid)
    softmax_top2<<<64, 256>>>(b2, bi2, out);

    // 5) join, then top-k net + scan (aux folded into scan)
    cudaStreamWaitEvent(0, ev1, 0);
    tk_matvec_kernel<<<64, 256>>>(Wt1, bt1, Wt2, bt2);
    scan_scatter16_kernel<<<NE, 256>>>(out);
}